// round 11
// baseline (speedup 1.0000x reference)
#include <cuda_runtime.h>
#include <cstdint>
#include <mma.h>

using namespace nvcuda;

#define NMAX 50000
#define EMAX 850000

// ---------------- scratch (device globals; no allocation allowed) ----------------
__device__ float  g_fs1[(size_t)NMAX * 256];
__device__ float  g_h1 [(size_t)NMAX * 256];
__device__ float  g_fs2[(size_t)NMAX * 128];
__device__ float  g_res2[(size_t)NMAX * 128];
__device__ float  g_agg2[(size_t)NMAX * 128];
__device__ float4 g_ew1[EMAX];
__device__ float4 g_ew2[EMAX];
__device__ float4 g_el1[NMAX];
__device__ float4 g_er1[NMAX];
__device__ float4 g_el2[NMAX];
__device__ float4 g_er2[NMAX];
__device__ float4 g_inv1[NMAX];
__device__ float4 g_inv2[NMAX];
__device__ int    g_rowptr[NMAX + 1];
__device__ int    g_cursor[NMAX];
__device__ int    g_deg[NMAX];
__device__ int    g_srcs[EMAX];
__device__ float  g_VU1[8 * 256];
__device__ float  g_VU2[8 * 256];
__device__ int    g_bsum[128];

__device__ __forceinline__ float lrelu(float x) { return x > 0.f ? x : 0.2f * x; }
__device__ __forceinline__ float eluf (float x) { return x > 0.f ? x : expm1f(x); }

__device__ __forceinline__ void cpa16(float* s, const float* g, bool pred) {
    unsigned int sa = (unsigned int)__cvta_generic_to_shared(s);
    int sz = pred ? 16 : 0;
    asm volatile("cp.async.cg.shared.global [%0], [%1], 16, %2;\n" :: "r"(sa), "l"(g), "r"(sz));
}
__device__ __forceinline__ void cpa_commit() { asm volatile("cp.async.commit_group;\n"); }

// ---------------- CSR build ----------------
__global__ void k_zero(int* __restrict__ deg, int n) {
    int i = blockIdx.x * blockDim.x + threadIdx.x;
    if (i < n) deg[i] = 0;
}

__global__ void k_hist(const int* __restrict__ dst, int* __restrict__ deg, int E) {
    int i = blockIdx.x * blockDim.x + threadIdx.x;
    if (i < E) atomicAdd(&deg[dst[i]], 1);
}

__global__ void k_scan_chunk(const int* __restrict__ deg, int* __restrict__ rowptr,
                             int* __restrict__ bsum, int n) {
    __shared__ int sm[1024];
    int b = blockIdx.x, t = threadIdx.x;
    int i = b * 1024 + t;
    int x = (i < n) ? deg[i] : 0;
    sm[t] = x;
    __syncthreads();
    for (int off = 1; off < 1024; off <<= 1) {
        int v = (t >= off) ? sm[t - off] : 0;
        __syncthreads();
        sm[t] += v;
        __syncthreads();
    }
    if (i < n) rowptr[i] = sm[t] - x;
    if (t == 1023) bsum[b] = sm[1023];
}

__global__ void k_scan_add(int* __restrict__ rowptr, int* __restrict__ cursor,
                           const int* __restrict__ bsum, int n, int E, int nch) {
    __shared__ int sb[64];
    if (threadIdx.x < 64) sb[threadIdx.x] = (threadIdx.x < nch) ? bsum[threadIdx.x] : 0;
    __syncthreads();
    int i = blockIdx.x * blockDim.x + threadIdx.x;
    if (i < n) {
        int ch = i >> 10, off = 0;
        for (int j = 0; j < ch; j++) off += sb[j];
        int v = rowptr[i] + off;
        rowptr[i] = v;
        cursor[i] = v;
        if (i == 0) rowptr[n] = E;
    }
}

__global__ void k_scatter(const int* __restrict__ src, const int* __restrict__ dst,
                          int* __restrict__ cursor, int* __restrict__ srcs, int E) {
    int i = blockIdx.x * blockDim.x + threadIdx.x;
    if (i < E) {
        int d = dst[i];
        int pos = atomicAdd(&cursor[d], 1);
        srcs[pos] = src[i];
    }
}

// ---------------- attention-score projection vectors ----------------
template <int DHH>
__global__ void k_vecs(const float* __restrict__ Ws, const float* __restrict__ al,
                       const float* __restrict__ Wd, const float* __restrict__ ar,
                       float* __restrict__ out) {
    int id = blockIdx.x * blockDim.x + threadIdx.x;
    if (id >= 256 * 8) return;
    int i = id >> 3, j = id & 7, h = j & 3;
    const float* W = (j < 4) ? Ws : Wd;
    const float* a = (j < 4) ? al : ar;
    float s = 0.f;
#pragma unroll 4
    for (int d = 0; d < DHH; d++) s += W[i * (4 * DHH) + h * DHH + d] * a[h * DHH + d];
    out[j * 256 + i] = s;
}

// el/er for every node: warp per node, X is [n,256]
__global__ void k_eler(const float* __restrict__ X, const float* __restrict__ VU,
                       float4* __restrict__ el, float4* __restrict__ er, int n) {
    __shared__ float sVU[8 * 256];
    for (int i = threadIdx.x; i < 8 * 256; i += blockDim.x) sVU[i] = VU[i];
    __syncthreads();
    int w = (blockIdx.x * blockDim.x + threadIdx.x) >> 5;
    int lane = threadIdx.x & 31;
    if (w >= n) return;
    const float* x = X + (size_t)w * 256;
    float acc[8] = {0, 0, 0, 0, 0, 0, 0, 0};
#pragma unroll
    for (int k = 0; k < 8; k++) {
        int idx = lane + 32 * k;
        float v = x[idx];
#pragma unroll
        for (int j = 0; j < 8; j++) acc[j] = fmaf(v, sVU[j * 256 + idx], acc[j]);
    }
#pragma unroll
    for (int off = 16; off; off >>= 1)
#pragma unroll
        for (int j = 0; j < 8; j++) acc[j] += __shfl_xor_sync(0xffffffffu, acc[j], off);
    if (lane == 0) {
        el[w] = make_float4(acc[0], acc[1], acc[2], acc[3]);
        er[w] = make_float4(acc[4], acc[5], acc[6], acc[7]);
    }
}

// ---------------- segment softmax (passes 1+2): ew = exp, inv = 1/sum ----------------
__global__ void k_soft(const int* __restrict__ rowptr, const int* __restrict__ srcs,
                       const float4* __restrict__ el, const float4* __restrict__ er,
                       float4* __restrict__ ew, float4* __restrict__ inv, int n) {
    int w = (blockIdx.x * blockDim.x + threadIdx.x) >> 5;
    if (w >= n) return;
    int lane = threadIdx.x & 31;
    int s0 = rowptr[w], s1 = rowptr[w + 1];
    float4 erv = er[w];

    float m0 = -1e30f, m1 = -1e30f, m2 = -1e30f, m3 = -1e30f;
    for (int e = s0 + lane; e < s1; e += 32) {
        float4 ev = el[srcs[e]];
        m0 = fmaxf(m0, lrelu(ev.x + erv.x));
        m1 = fmaxf(m1, lrelu(ev.y + erv.y));
        m2 = fmaxf(m2, lrelu(ev.z + erv.z));
        m3 = fmaxf(m3, lrelu(ev.w + erv.w));
    }
#pragma unroll
    for (int off = 16; off; off >>= 1) {
        m0 = fmaxf(m0, __shfl_xor_sync(0xffffffffu, m0, off));
        m1 = fmaxf(m1, __shfl_xor_sync(0xffffffffu, m1, off));
        m2 = fmaxf(m2, __shfl_xor_sync(0xffffffffu, m2, off));
        m3 = fmaxf(m3, __shfl_xor_sync(0xffffffffu, m3, off));
    }
    float t0 = 0.f, t1 = 0.f, t2 = 0.f, t3 = 0.f;
    for (int e = s0 + lane; e < s1; e += 32) {
        float4 ev = el[srcs[e]];
        float4 x;
        x.x = __expf(lrelu(ev.x + erv.x) - m0);
        x.y = __expf(lrelu(ev.y + erv.y) - m1);
        x.z = __expf(lrelu(ev.z + erv.z) - m2);
        x.w = __expf(lrelu(ev.w + erv.w) - m3);
        ew[e] = x;
        t0 += x.x; t1 += x.y; t2 += x.z; t3 += x.w;
    }
#pragma unroll
    for (int off = 16; off; off >>= 1) {
        t0 += __shfl_xor_sync(0xffffffffu, t0, off);
        t1 += __shfl_xor_sync(0xffffffffu, t1, off);
        t2 += __shfl_xor_sync(0xffffffffu, t2, off);
        t3 += __shfl_xor_sync(0xffffffffu, t3, off);
    }
    if (lane == 0) inv[w] = make_float4(1.f / t0, 1.f / t1, 1.f / t2, 1.f / t3);
}

// ---------------- tf32 WMMA GEMM, 3-stage cp.async pipeline ----------------
#define SMA_ST (128 * 36)
#define SMB_ST (32 * 68)
#define GEMM_SMEM (3 * (SMA_ST + SMB_ST) * 4)

template <int NCOLS>
__global__ void __launch_bounds__(256, 2) k_gemm(const float* __restrict__ A,
                                                 const float* __restrict__ B,
                                                 float* __restrict__ C, int M) {
    extern __shared__ float smx[];
    int colBase = blockIdx.y * 64;
    int rowBase = blockIdx.x * 128;
    int tid = threadIdx.x, lane = tid & 31, warp = tid >> 5;
    int wm = warp & 3, wn = warp >> 2;

    wmma::fragment<wmma::accumulator, 16, 16, 8, float> acc[2][2];
#pragma unroll
    for (int i = 0; i < 2; i++)
#pragma unroll
        for (int j = 0; j < 2; j++) wmma::fill_fragment(acc[i][j], 0.0f);

    auto loadTile = [&](int it) {
        int stage = it % 3;
        int k0 = it * 32;
        float* As = smx + stage * (SMA_ST + SMB_ST);
        float* Bs = As + SMA_ST;
#pragma unroll
        for (int i = 0; i < 4; i++) {
            int f4 = i * 256 + tid;
            int r = f4 >> 3, c4 = f4 & 7;
            int gr = rowBase + r;
            int grc = (gr < M) ? gr : (M - 1);
            cpa16(&As[r * 36 + c4 * 4], &A[(size_t)grc * 256 + k0 + c4 * 4], gr < M);
        }
#pragma unroll
        for (int i = 0; i < 2; i++) {
            int f4 = i * 256 + tid;
            int r = f4 >> 4, c4 = f4 & 15;
            cpa16(&Bs[r * 68 + c4 * 4], &B[(size_t)(k0 + r) * NCOLS + colBase + c4 * 4], true);
        }
    };

    loadTile(0); cpa_commit();
    loadTile(1); cpa_commit();

#pragma unroll 1
    for (int it = 0; it < 8; it++) {
        asm volatile("cp.async.wait_group 1;\n");
        __syncthreads();
        if (it + 2 < 8) { loadTile(it + 2); cpa_commit(); }
        const float* As = smx + (it % 3) * (SMA_ST + SMB_ST);
        const float* Bs = As + SMA_ST;
#pragma unroll
        for (int kk = 0; kk < 32; kk += 8) {
            wmma::fragment<wmma::matrix_b, 16, 16, 8, wmma::precision::tf32, wmma::row_major> bf[2];
#pragma unroll
            for (int j = 0; j < 2; j++) {
                wmma::load_matrix_sync(bf[j], Bs + kk * 68 + wn * 32 + j * 16, 68);
#pragma unroll
                for (int t = 0; t < bf[j].num_elements; t++)
                    bf[j].x[t] = wmma::__float_to_tf32(bf[j].x[t]);
            }
#pragma unroll
            for (int i = 0; i < 2; i++) {
                wmma::fragment<wmma::matrix_a, 16, 16, 8, wmma::precision::tf32, wmma::row_major> af;
                wmma::load_matrix_sync(af, As + (wm * 32 + i * 16) * 36 + kk, 36);
#pragma unroll
                for (int t = 0; t < af.num_elements; t++)
                    af.x[t] = wmma::__float_to_tf32(af.x[t]);
#pragma unroll
                for (int j = 0; j < 2; j++) wmma::mma_sync(acc[i][j], af, bf[j], acc[i][j]);
            }
        }
    }
    asm volatile("cp.async.wait_group 0;\n");
    __syncthreads();

#pragma unroll
    for (int i = 0; i < 2; i++) {
        int r0 = rowBase + wm * 32 + i * 16;
#pragma unroll
        for (int j = 0; j < 2; j++) {
            int c0 = colBase + wn * 32 + j * 16;
            if (r0 + 16 <= M) {
                wmma::store_matrix_sync(&C[(size_t)r0 * NCOLS + c0], acc[i][j], NCOLS, wmma::mem_row_major);
            } else if (r0 < M) {
                float* stg = smx + warp * 320;
                wmma::store_matrix_sync(stg, acc[i][j], 20, wmma::mem_row_major);
                __syncwarp();
                for (int idx = lane; idx < 256; idx += 32) {
                    int rr = idx >> 4, cc = idx & 15;
                    if (r0 + rr < M) C[(size_t)(r0 + rr) * NCOLS + c0 + cc] = stg[rr * 20 + cc];
                }
                __syncwarp();
            }
        }
    }
}

// ---------------- weighted gather (pass 3) ----------------
// L1: channels lane*4 (head lane>>4 pair) + residual(h) + elu -> h1 [n,256]
__global__ void k_gather1(const int* __restrict__ rowptr, const int* __restrict__ srcs,
                          const float* __restrict__ fs, const float* __restrict__ resid,
                          const float4* __restrict__ inv, const float4* __restrict__ ew,
                          float* __restrict__ out, int n) {
    int w = (blockIdx.x * blockDim.x + threadIdx.x) >> 5;
    if (w >= n) return;
    int lane = threadIdx.x & 31;
    int s0 = rowptr[w], s1 = rowptr[w + 1];
    float4 iv = inv[w];
    float ia = (lane < 16) ? iv.x : iv.y;
    float ib = (lane < 16) ? iv.z : iv.w;

    float4 a0 = make_float4(0, 0, 0, 0), a1 = make_float4(0, 0, 0, 0);
    const float4* fp = reinterpret_cast<const float4*>(fs);
    int e = s0;
    for (; e + 4 <= s1; e += 4) {
        int sA = srcs[e], sB = srcs[e + 1], sC = srcs[e + 2], sD = srcs[e + 3];
        float4 wA = ew[e], wB = ew[e + 1], wC = ew[e + 2], wD = ew[e + 3];
        const float4* pA = fp + (size_t)sA * 64 + lane;
        const float4* pB = fp + (size_t)sB * 64 + lane;
        const float4* pC = fp + (size_t)sC * 64 + lane;
        const float4* pD = fp + (size_t)sD * 64 + lane;
        float4 fA0 = pA[0], fA1 = pA[32];
        float4 fB0 = pB[0], fB1 = pB[32];
        float4 fC0 = pC[0], fC1 = pC[32];
        float4 fD0 = pD[0], fD1 = pD[32];
        float wa, wb;
        wa = ((lane < 16) ? wA.x : wA.y) * ia; wb = ((lane < 16) ? wA.z : wA.w) * ib;
        a0.x = fmaf(wa, fA0.x, a0.x); a0.y = fmaf(wa, fA0.y, a0.y);
        a0.z = fmaf(wa, fA0.z, a0.z); a0.w = fmaf(wa, fA0.w, a0.w);
        a1.x = fmaf(wb, fA1.x, a1.x); a1.y = fmaf(wb, fA1.y, a1.y);
        a1.z = fmaf(wb, fA1.z, a1.z); a1.w = fmaf(wb, fA1.w, a1.w);
        wa = ((lane < 16) ? wB.x : wB.y) * ia; wb = ((lane < 16) ? wB.z : wB.w) * ib;
        a0.x = fmaf(wa, fB0.x, a0.x); a0.y = fmaf(wa, fB0.y, a0.y);
        a0.z = fmaf(wa, fB0.z, a0.z); a0.w = fmaf(wa, fB0.w, a0.w);
        a1.x = fmaf(wb, fB1.x, a1.x); a1.y = fmaf(wb, fB1.y, a1.y);
        a1.z = fmaf(wb, fB1.z, a1.z); a1.w = fmaf(wb, fB1.w, a1.w);
        wa = ((lane < 16) ? wC.x : wC.y) * ia; wb = ((lane < 16) ? wC.z : wC.w) * ib;
        a0.x = fmaf(wa, fC0.x, a0.x); a0.y = fmaf(wa, fC0.y, a0.y);
        a0.z = fmaf(wa, fC0.z, a0.z); a0.w = fmaf(wa, fC0.w, a0.w);
        a1.x = fmaf(wb, fC1.x, a1.x); a1.y = fmaf(wb, fC1.y, a1.y);
        a1.z = fmaf(wb, fC1.z, a1.z); a1.w = fmaf(wb, fC1.w, a1.w);
        wa = ((lane < 16) ? wD.x : wD.y) * ia; wb = ((lane < 16) ? wD.z : wD.w) * ib;
        a0.x = fmaf(wa, fD0.x, a0.x); a0.y = fmaf(wa, fD0.y, a0.y);
        a0.z = fmaf(wa, fD0.z, a0.z); a0.w = fmaf(wa, fD0.w, a0.w);
        a1.x = fmaf(wb, fD1.x, a1.x); a1.y = fmaf(wb, fD1.y, a1.y);
        a1.z = fmaf(wb, fD1.z, a1.z); a1.w = fmaf(wb, fD1.w, a1.w);
    }
    for (; e < s1; e++) {
        int s = srcs[e];
        float4 w4 = ew[e];
        float wa = ((lane < 16) ? w4.x : w4.y) * ia;
        float wb = ((lane < 16) ? w4.z : w4.w) * ib;
        float4 f0 = fp[(size_t)s * 64 + lane];
        float4 f1 = fp[(size_t)s * 64 + 32 + lane];
        a0.x = fmaf(wa, f0.x, a0.x); a0.y = fmaf(wa, f0.y, a0.y);
        a0.z = fmaf(wa, f0.z, a0.z); a0.w = fmaf(wa, f0.w, a0.w);
        a1.x = fmaf(wb, f1.x, a1.x); a1.y = fmaf(wb, f1.y, a1.y);
        a1.z = fmaf(wb, f1.z, a1.z); a1.w = fmaf(wb, f1.w, a1.w);
    }
    const float4* rp = reinterpret_cast<const float4*>(resid);
    float4 r0 = rp[(size_t)w * 64 + lane];
    float4 r1 = rp[(size_t)w * 64 + 32 + lane];
    float4 o0, o1;
    o0.x = eluf(a0.x + r0.x); o0.y = eluf(a0.y + r0.y);
    o0.z = eluf(a0.z + r0.z); o0.w = eluf(a0.w + r0.w);
    o1.x = eluf(a1.x + r1.x); o1.y = eluf(a1.y + r1.y);
    o1.z = eluf(a1.z + r1.z); o1.w = eluf(a1.w + r1.w);
    float4* op = reinterpret_cast<float4*>(out);
    op[(size_t)w * 64 + lane] = o0;
    op[(size_t)w * 64 + 32 + lane] = o1;
}

// L2 gather only: channels 4*lane, head lane>>3 -> agg2 [n,128] (no residual/mean here)
__global__ void k_gather2(const int* __restrict__ rowptr, const int* __restrict__ srcs,
                          const float* __restrict__ fs, const float4* __restrict__ inv,
                          const float4* __restrict__ ew, float* __restrict__ agg, int n) {
    int w = (blockIdx.x * blockDim.x + threadIdx.x) >> 5;
    if (w >= n) return;
    int lane = threadIdx.x & 31;
    int s0 = rowptr[w], s1 = rowptr[w + 1];
    float4 iv = inv[w];
    int hsel = lane >> 3;
    float isel = (hsel < 2) ? (hsel ? iv.y : iv.x) : (hsel == 2 ? iv.z : iv.w);

    float4 a0 = make_float4(0, 0, 0, 0);
    const float4* fp = reinterpret_cast<const float4*>(fs);
    int e = s0;
    for (; e + 4 <= s1; e += 4) {
        int sA = srcs[e], sB = srcs[e + 1], sC = srcs[e + 2], sD = srcs[e + 3];
        float4 wA = ew[e], wB = ew[e + 1], wC = ew[e + 2], wD = ew[e + 3];
        float4 fA = fp[(size_t)sA * 32 + lane];
        float4 fB = fp[(size_t)sB * 32 + lane];
        float4 fC = fp[(size_t)sC * 32 + lane];
        float4 fD = fp[(size_t)sD * 32 + lane];
        float wa;
        wa = ((hsel < 2) ? (hsel ? wA.y : wA.x) : (hsel == 2 ? wA.z : wA.w)) * isel;
        a0.x = fmaf(wa, fA.x, a0.x); a0.y = fmaf(wa, fA.y, a0.y);
        a0.z = fmaf(wa, fA.z, a0.z); a0.w = fmaf(wa, fA.w, a0.w);
        wa = ((hsel < 2) ? (hsel ? wB.y : wB.x) : (hsel == 2 ? wB.z : wB.w)) * isel;
        a0.x = fmaf(wa, fB.x, a0.x); a0.y = fmaf(wa, fB.y, a0.y);
        a0.z = fmaf(wa, fB.z, a0.z); a0.w = fmaf(wa, fB.w, a0.w);
        wa = ((hsel < 2) ? (hsel ? wC.y : wC.x) : (hsel == 2 ? wC.z : wC.w)) * isel;
        a0.x = fmaf(wa, fC.x, a0.x); a0.y = fmaf(wa, fC.y, a0.y);
        a0.z = fmaf(wa, fC.z, a0.z); a0.w = fmaf(wa, fC.w, a0.w);
        wa = ((hsel < 2) ? (hsel ? wD.y : wD.x) : (hsel == 2 ? wD.z : wD.w)) * isel;
        a0.x = fmaf(wa, fD.x, a0.x); a0.y = fmaf(wa, fD.y, a0.y);
        a0.z = fmaf(wa, fD.z, a0.z); a0.w = fmaf(wa, fD.w, a0.w);
    }
    for (; e < s1; e++) {
        int s = srcs[e];
        float4 w4 = ew[e];
        float wa = ((hsel < 2) ? (hsel ? w4.y : w4.x) : (hsel == 2 ? w4.z : w4.w)) * isel;
        float4 f0 = fp[(size_t)s * 32 + lane];
        a0.x = fmaf(wa, f0.x, a0.x); a0.y = fmaf(wa, f0.y, a0.y);
        a0.z = fmaf(wa, f0.z, a0.z); a0.w = fmaf(wa, f0.w, a0.w);
    }
    reinterpret_cast<float4*>(agg)[(size_t)w * 32 + lane] = a0;
}

// final: out[n,32] = mean_h(agg2[n,h,32] + res2[n,h,32])
__global__ void k_fin2(const float* __restrict__ agg, const float* __restrict__ res,
                       float* __restrict__ out, int n) {
    int id = blockIdx.x * blockDim.x + threadIdx.x;
    int w = id >> 3, j = id & 7;
    if (w >= n) return;
    const float4* ap = reinterpret_cast<const float4*>(agg);
    const float4* rp = reinterpret_cast<const float4*>(res);
    float4 s = make_float4(0, 0, 0, 0);
#pragma unroll
    for (int h = 0; h < 4; h++) {
        float4 a = ap[(size_t)w * 32 + h * 8 + j];
        float4 r = rp[(size_t)w * 32 + h * 8 + j];
        s.x += a.x + r.x; s.y += a.y + r.y; s.z += a.z + r.z; s.w += a.w + r.w;
    }
    s.x *= 0.25f; s.y *= 0.25f; s.z *= 0.25f; s.w *= 0.25f;
    reinterpret_cast<float4*>(out)[(size_t)w * 8 + j] = s;
}

// ---------------- launcher with fork/join overlap ----------------
extern "C" void kernel_launch(void* const* d_in, const int* in_sizes, int n_in,
                              void* d_out, int out_size) {
    const float* h   = (const float*)d_in[0];
    const int*   src = (const int*)d_in[1];
    const int*   dst = (const int*)d_in[2];
    const float* W1s = (const float*)d_in[3];
    const float* W1d = (const float*)d_in[4];
    const float* al1 = (const float*)d_in[5];
    const float* ar1 = (const float*)d_in[6];
    const float* W2s = (const float*)d_in[7];
    const float* W2d = (const float*)d_in[8];
    const float* al2 = (const float*)d_in[9];
    const float* ar2 = (const float*)d_in[10];
    const float* Wr2 = (const float*)d_in[11];
    float* out = (float*)d_out;

    int Nn = in_sizes[0] / 256;
    int E  = in_sizes[1];
    if (Nn > NMAX) Nn = NMAX;
    if (E  > EMAX) E  = EMAX;

    float *fs1, *h1, *fs2, *res2, *agg2, *VU1, *VU2;
    float4 *el1, *er1, *el2, *er2, *ew1, *ew2, *inv1, *inv2;
    int *rowptr, *cursor, *deg, *srcs, *bsum;
    cudaGetSymbolAddress((void**)&fs1,    g_fs1);
    cudaGetSymbolAddress((void**)&h1,     g_h1);
    cudaGetSymbolAddress((void**)&fs2,    g_fs2);
    cudaGetSymbolAddress((void**)&res2,   g_res2);
    cudaGetSymbolAddress((void**)&agg2,   g_agg2);
    cudaGetSymbolAddress((void**)&VU1,    g_VU1);
    cudaGetSymbolAddress((void**)&VU2,    g_VU2);
    cudaGetSymbolAddress((void**)&el1,    g_el1);
    cudaGetSymbolAddress((void**)&er1,    g_er1);
    cudaGetSymbolAddress((void**)&el2,    g_el2);
    cudaGetSymbolAddress((void**)&er2,    g_er2);
    cudaGetSymbolAddress((void**)&ew1,    g_ew1);
    cudaGetSymbolAddress((void**)&ew2,    g_ew2);
    cudaGetSymbolAddress((void**)&inv1,   g_inv1);
    cudaGetSymbolAddress((void**)&inv2,   g_inv2);
    cudaGetSymbolAddress((void**)&rowptr, g_rowptr);
    cudaGetSymbolAddress((void**)&cursor, g_cursor);
    cudaGetSymbolAddress((void**)&deg,    g_deg);
    cudaGetSymbolAddress((void**)&srcs,   g_srcs);
    cudaGetSymbolAddress((void**)&bsum,   g_bsum);

    cudaFuncSetAttribute(k_gemm<256>, cudaFuncAttributeMaxDynamicSharedMemorySize, GEMM_SMEM);
    cudaFuncSetAttribute(k_gemm<128>, cudaFuncAttributeMaxDynamicSharedMemorySize, GEMM_SMEM);

    int wblocks = (Nn * 32 + 255) / 256;
    int nch = (Nn + 1023) / 1024;
    dim3 g1((Nn + 127) / 128, 4);
    dim3 g2((Nn + 127) / 128, 2);

    cudaStream_t side;
    cudaStreamCreateWithFlags(&side, cudaStreamNonBlocking);
    cudaEvent_t evFork1, evJoin1, evFork2, evSoft2, evA, evB;
    cudaEventCreateWithFlags(&evFork1, cudaEventDisableTiming);
    cudaEventCreateWithFlags(&evJoin1, cudaEventDisableTiming);
    cudaEventCreateWithFlags(&evFork2, cudaEventDisableTiming);
    cudaEventCreateWithFlags(&evSoft2, cudaEventDisableTiming);
    cudaEventCreateWithFlags(&evA, cudaEventDisableTiming);
    cudaEventCreateWithFlags(&evB, cudaEventDisableTiming);

    // ---- fork 1: CSR + eler1 + soft1 on side; GEMM1 on main ----
    cudaEventRecord(evFork1, 0);
    cudaStreamWaitEvent(side, evFork1, 0);

    k_zero<<<(Nn + 255) / 256, 256, 0, side>>>(deg, Nn);
    k_hist<<<(E + 255) / 256, 256, 0, side>>>(dst, deg, E);
    k_scan_chunk<<<nch, 1024, 0, side>>>(deg, rowptr, bsum, Nn);
    k_scan_add<<<(Nn + 255) / 256, 256, 0, side>>>(rowptr, cursor, bsum, Nn, E, nch);
    k_scatter<<<(E + 255) / 256, 256, 0, side>>>(src, dst, cursor, srcs, E);
    k_vecs<64><<<8, 256, 0, side>>>(W1s, al1, W1d, ar1, VU1);
    k_eler<<<wblocks, 256, 0, side>>>(h, VU1, el1, er1, Nn);
    k_soft<<<wblocks, 256, 0, side>>>(rowptr, srcs, el1, er1, ew1, inv1, Nn);
    cudaEventRecord(evJoin1, side);

    k_gemm<256><<<g1, 256, GEMM_SMEM>>>(h, W1s, fs1, Nn);

    cudaStreamWaitEvent(0, evJoin1, 0);
    k_gather1<<<wblocks, 256>>>(rowptr, srcs, fs1, h, inv1, ew1, h1, Nn);

    // ---- fork 2: eler2 + soft2 on side; GEMM2a(fs2) on main;
    //      GEMM2b(res2) on side after GEMM2a, concurrent with gather2 ----
    cudaEventRecord(evFork2, 0);
    cudaStreamWaitEvent(side, evFork2, 0);

    k_vecs<32><<<8, 256, 0, side>>>(W2s, al2, W2d, ar2, VU2);
    k_eler<<<wblocks, 256, 0, side>>>(h1, VU2, el2, er2, Nn);
    k_soft<<<wblocks, 256, 0, side>>>(rowptr, srcs, el2, er2, ew2, inv2, Nn);
    cudaEventRecord(evSoft2, side);

    k_gemm<128><<<g2, 256, GEMM_SMEM>>>(h1, W2s, fs2, Nn);
    cudaEventRecord(evA, 0);

    cudaStreamWaitEvent(side, evA, 0);
    k_gemm<128><<<g2, 256, GEMM_SMEM, side>>>(h1, Wr2, res2, Nn);
    cudaEventRecord(evB, side);

    cudaStreamWaitEvent(0, evSoft2, 0);
    k_gather2<<<wblocks, 256>>>(rowptr, srcs, fs2, inv2, ew2, agg2, Nn);

    cudaStreamWaitEvent(0, evB, 0);
    k_fin2<<<(Nn * 8 + 255) / 256, 256>>>(agg2, res2, out, Nn);
}

// round 12
// speedup vs baseline: 1.0274x; 1.0274x over previous
#include <cuda_runtime.h>
#include <cstdint>
#include <mma.h>

using namespace nvcuda;

#define NMAX 50000
#define EMAX 850000

// ---------------- scratch (device globals; no allocation allowed) ----------------
__device__ float  g_fs1[(size_t)NMAX * 256];
__device__ float  g_h1 [(size_t)NMAX * 256];
__device__ float  g_fs2[(size_t)NMAX * 128];
__device__ float  g_res2[(size_t)NMAX * 128];
__device__ float4 g_ew1[EMAX];
__device__ float4 g_ew2[EMAX];
__device__ float4 g_el1[NMAX];
__device__ float4 g_er1[NMAX];
__device__ float4 g_el2[NMAX];
__device__ float4 g_er2[NMAX];
__device__ float4 g_inv1[NMAX];
__device__ float4 g_inv2[NMAX];
__device__ int    g_rowptr[NMAX + 1];
__device__ int    g_cursor[NMAX];
__device__ int    g_deg[NMAX];
__device__ int    g_srcs[EMAX];
__device__ float  g_VU1[8 * 256];
__device__ float  g_VU2[8 * 256];
__device__ int    g_bsum[128];

__device__ __forceinline__ float lrelu(float x) { return x > 0.f ? x : 0.2f * x; }
__device__ __forceinline__ float eluf (float x) { return x > 0.f ? x : expm1f(x); }

__device__ __forceinline__ void cpa16(float* s, const float* g, bool pred) {
    unsigned int sa = (unsigned int)__cvta_generic_to_shared(s);
    int sz = pred ? 16 : 0;
    asm volatile("cp.async.cg.shared.global [%0], [%1], 16, %2;\n" :: "r"(sa), "l"(g), "r"(sz));
}
__device__ __forceinline__ void cpa_commit() { asm volatile("cp.async.commit_group;\n"); }

// ---------------- CSR build ----------------
__global__ void k_zero(int* __restrict__ deg, int n) {
    int i = blockIdx.x * blockDim.x + threadIdx.x;
    if (i < n) deg[i] = 0;
}

__global__ void k_hist(const int* __restrict__ dst, int* __restrict__ deg, int E) {
    int i = blockIdx.x * blockDim.x + threadIdx.x;
    if (i < E) atomicAdd(&deg[dst[i]], 1);
}

__global__ void k_scan_chunk(const int* __restrict__ deg, int* __restrict__ rowptr,
                             int* __restrict__ bsum, int n) {
    __shared__ int sm[1024];
    int b = blockIdx.x, t = threadIdx.x;
    int i = b * 1024 + t;
    int x = (i < n) ? deg[i] : 0;
    sm[t] = x;
    __syncthreads();
    for (int off = 1; off < 1024; off <<= 1) {
        int v = (t >= off) ? sm[t - off] : 0;
        __syncthreads();
        sm[t] += v;
        __syncthreads();
    }
    if (i < n) rowptr[i] = sm[t] - x;
    if (t == 1023) bsum[b] = sm[1023];
}

__global__ void k_scan_add(int* __restrict__ rowptr, int* __restrict__ cursor,
                           const int* __restrict__ bsum, int n, int E, int nch) {
    __shared__ int sb[64];
    if (threadIdx.x < 64) sb[threadIdx.x] = (threadIdx.x < nch) ? bsum[threadIdx.x] : 0;
    __syncthreads();
    int i = blockIdx.x * blockDim.x + threadIdx.x;
    if (i < n) {
        int ch = i >> 10, off = 0;
        for (int j = 0; j < ch; j++) off += sb[j];
        int v = rowptr[i] + off;
        rowptr[i] = v;
        cursor[i] = v;
        if (i == 0) rowptr[n] = E;
    }
}

__global__ void k_scatter(const int* __restrict__ src, const int* __restrict__ dst,
                          int* __restrict__ cursor, int* __restrict__ srcs, int E) {
    int i = blockIdx.x * blockDim.x + threadIdx.x;
    if (i < E) {
        int d = dst[i];
        int pos = atomicAdd(&cursor[d], 1);
        srcs[pos] = src[i];
    }
}

// ---------------- attention-score projection vectors ----------------
template <int DHH>
__global__ void k_vecs(const float* __restrict__ Ws, const float* __restrict__ al,
                       const float* __restrict__ Wd, const float* __restrict__ ar,
                       float* __restrict__ out) {
    int id = blockIdx.x * blockDim.x + threadIdx.x;
    if (id >= 256 * 8) return;
    int i = id >> 3, j = id & 7, h = j & 3;
    const float* W = (j < 4) ? Ws : Wd;
    const float* a = (j < 4) ? al : ar;
    float s = 0.f;
#pragma unroll 4
    for (int d = 0; d < DHH; d++) s += W[i * (4 * DHH) + h * DHH + d] * a[h * DHH + d];
    out[j * 256 + i] = s;
}

// el/er for every node: warp per node, X is [n,256]
__global__ void k_eler(const float* __restrict__ X, const float* __restrict__ VU,
                       float4* __restrict__ el, float4* __restrict__ er, int n) {
    __shared__ float sVU[8 * 256];
    for (int i = threadIdx.x; i < 8 * 256; i += blockDim.x) sVU[i] = VU[i];
    __syncthreads();
    int w = (blockIdx.x * blockDim.x + threadIdx.x) >> 5;
    int lane = threadIdx.x & 31;
    if (w >= n) return;
    const float* x = X + (size_t)w * 256;
    float acc[8] = {0, 0, 0, 0, 0, 0, 0, 0};
#pragma unroll
    for (int k = 0; k < 8; k++) {
        int idx = lane + 32 * k;
        float v = x[idx];
#pragma unroll
        for (int j = 0; j < 8; j++) acc[j] = fmaf(v, sVU[j * 256 + idx], acc[j]);
    }
#pragma unroll
    for (int off = 16; off; off >>= 1)
#pragma unroll
        for (int j = 0; j < 8; j++) acc[j] += __shfl_xor_sync(0xffffffffu, acc[j], off);
    if (lane == 0) {
        el[w] = make_float4(acc[0], acc[1], acc[2], acc[3]);
        er[w] = make_float4(acc[4], acc[5], acc[6], acc[7]);
    }
}

// ---------------- segment softmax (passes 1+2): ew = exp, inv = 1/sum ----------------
__global__ void k_soft(const int* __restrict__ rowptr, const int* __restrict__ srcs,
                       const float4* __restrict__ el, const float4* __restrict__ er,
                       float4* __restrict__ ew, float4* __restrict__ inv, int n) {
    int w = (blockIdx.x * blockDim.x + threadIdx.x) >> 5;
    if (w >= n) return;
    int lane = threadIdx.x & 31;
    int s0 = rowptr[w], s1 = rowptr[w + 1];
    float4 erv = er[w];

    float m0 = -1e30f, m1 = -1e30f, m2 = -1e30f, m3 = -1e30f;
    for (int e = s0 + lane; e < s1; e += 32) {
        float4 ev = el[srcs[e]];
        m0 = fmaxf(m0, lrelu(ev.x + erv.x));
        m1 = fmaxf(m1, lrelu(ev.y + erv.y));
        m2 = fmaxf(m2, lrelu(ev.z + erv.z));
        m3 = fmaxf(m3, lrelu(ev.w + erv.w));
    }
#pragma unroll
    for (int off = 16; off; off >>= 1) {
        m0 = fmaxf(m0, __shfl_xor_sync(0xffffffffu, m0, off));
        m1 = fmaxf(m1, __shfl_xor_sync(0xffffffffu, m1, off));
        m2 = fmaxf(m2, __shfl_xor_sync(0xffffffffu, m2, off));
        m3 = fmaxf(m3, __shfl_xor_sync(0xffffffffu, m3, off));
    }
    float t0 = 0.f, t1 = 0.f, t2 = 0.f, t3 = 0.f;
    for (int e = s0 + lane; e < s1; e += 32) {
        float4 ev = el[srcs[e]];
        float4 x;
        x.x = __expf(lrelu(ev.x + erv.x) - m0);
        x.y = __expf(lrelu(ev.y + erv.y) - m1);
        x.z = __expf(lrelu(ev.z + erv.z) - m2);
        x.w = __expf(lrelu(ev.w + erv.w) - m3);
        ew[e] = x;
        t0 += x.x; t1 += x.y; t2 += x.z; t3 += x.w;
    }
#pragma unroll
    for (int off = 16; off; off >>= 1) {
        t0 += __shfl_xor_sync(0xffffffffu, t0, off);
        t1 += __shfl_xor_sync(0xffffffffu, t1, off);
        t2 += __shfl_xor_sync(0xffffffffu, t2, off);
        t3 += __shfl_xor_sync(0xffffffffu, t3, off);
    }
    if (lane == 0) inv[w] = make_float4(1.f / t0, 1.f / t1, 1.f / t2, 1.f / t3);
}

// ---------------- tf32 WMMA GEMM, 3-stage cp.async pipeline ----------------
// CTA tile 128x64, 8 warps 4m x 2n (warp tile 32x32), K=256 chunks of 32.
// If DUAL: grid.y >= TPG selects (B1,C1).
#define SMA_ST (128 * 36)
#define SMB_ST (32 * 68)
#define GEMM_SMEM (3 * (SMA_ST + SMB_ST) * 4)

template <int NCOLS, bool DUAL>
__global__ void __launch_bounds__(256, 2) k_gemm(const float* __restrict__ A,
                                                 const float* __restrict__ B0,
                                                 const float* __restrict__ B1,
                                                 float* __restrict__ C0,
                                                 float* __restrict__ C1, int M) {
    extern __shared__ float smx[];
    constexpr int TPG = NCOLS / 64;
    const float* B = (DUAL && (blockIdx.y >= TPG)) ? B1 : B0;
    float* C = (DUAL && (blockIdx.y >= TPG)) ? C1 : C0;
    int colBase = (DUAL ? (blockIdx.y % TPG) : blockIdx.y) * 64;
    int rowBase = blockIdx.x * 128;
    int tid = threadIdx.x, lane = tid & 31, warp = tid >> 5;
    int wm = warp & 3, wn = warp >> 2;

    wmma::fragment<wmma::accumulator, 16, 16, 8, float> acc[2][2];
#pragma unroll
    for (int i = 0; i < 2; i++)
#pragma unroll
        for (int j = 0; j < 2; j++) wmma::fill_fragment(acc[i][j], 0.0f);

    auto loadTile = [&](int it) {
        int stage = it % 3;
        int k0 = it * 32;
        float* As = smx + stage * (SMA_ST + SMB_ST);
        float* Bs = As + SMA_ST;
#pragma unroll
        for (int i = 0; i < 4; i++) {
            int f4 = i * 256 + tid;
            int r = f4 >> 3, c4 = f4 & 7;
            int gr = rowBase + r;
            int grc = (gr < M) ? gr : (M - 1);
            cpa16(&As[r * 36 + c4 * 4], &A[(size_t)grc * 256 + k0 + c4 * 4], gr < M);
        }
#pragma unroll
        for (int i = 0; i < 2; i++) {
            int f4 = i * 256 + tid;
            int r = f4 >> 4, c4 = f4 & 15;
            cpa16(&Bs[r * 68 + c4 * 4], &B[(size_t)(k0 + r) * NCOLS + colBase + c4 * 4], true);
        }
    };

    loadTile(0); cpa_commit();
    loadTile(1); cpa_commit();

#pragma unroll 1
    for (int it = 0; it < 8; it++) {
        asm volatile("cp.async.wait_group 1;\n");
        __syncthreads();
        if (it + 2 < 8) { loadTile(it + 2); cpa_commit(); }
        const float* As = smx + (it % 3) * (SMA_ST + SMB_ST);
        const float* Bs = As + SMA_ST;
#pragma unroll
        for (int kk = 0; kk < 32; kk += 8) {
            wmma::fragment<wmma::matrix_b, 16, 16, 8, wmma::precision::tf32, wmma::row_major> bf[2];
#pragma unroll
            for (int j = 0; j < 2; j++) {
                wmma::load_matrix_sync(bf[j], Bs + kk * 68 + wn * 32 + j * 16, 68);
#pragma unroll
                for (int t = 0; t < bf[j].num_elements; t++)
                    bf[j].x[t] = wmma::__float_to_tf32(bf[j].x[t]);
            }
#pragma unroll
            for (int i = 0; i < 2; i++) {
                wmma::fragment<wmma::matrix_a, 16, 16, 8, wmma::precision::tf32, wmma::row_major> af;
                wmma::load_matrix_sync(af, As + (wm * 32 + i * 16) * 36 + kk, 36);
#pragma unroll
                for (int t = 0; t < af.num_elements; t++)
                    af.x[t] = wmma::__float_to_tf32(af.x[t]);
#pragma unroll
                for (int j = 0; j < 2; j++) wmma::mma_sync(acc[i][j], af, bf[j], acc[i][j]);
            }
        }
    }
    asm volatile("cp.async.wait_group 0;\n");
    __syncthreads();

#pragma unroll
    for (int i = 0; i < 2; i++) {
        int r0 = rowBase + wm * 32 + i * 16;
#pragma unroll
        for (int j = 0; j < 2; j++) {
            int c0 = colBase + wn * 32 + j * 16;
            if (r0 + 16 <= M) {
                wmma::store_matrix_sync(&C[(size_t)r0 * NCOLS + c0], acc[i][j], NCOLS, wmma::mem_row_major);
            } else if (r0 < M) {
                float* stg = smx + warp * 320;
                wmma::store_matrix_sync(stg, acc[i][j], 20, wmma::mem_row_major);
                __syncwarp();
                for (int idx = lane; idx < 256; idx += 32) {
                    int rr = idx >> 4, cc = idx & 15;
                    if (r0 + rr < M) C[(size_t)(r0 + rr) * NCOLS + c0 + cc] = stg[rr * 20 + cc];
                }
                __syncwarp();
            }
        }
    }
}

// ---------------- weighted gather (pass 3) ----------------
// L1: channels lane*4 and 128+lane*4; head pair (lane>>4) -> + residual(h) + elu -> h1
__global__ void k_gather1(const int* __restrict__ rowptr, const int* __restrict__ srcs,
                          const float* __restrict__ fs, const float* __restrict__ resid,
                          const float4* __restrict__ inv, const float4* __restrict__ ew,
                          float* __restrict__ out, int n) {
    int w = (blockIdx.x * blockDim.x + threadIdx.x) >> 5;
    if (w >= n) return;
    int lane = threadIdx.x & 31;
    int s0 = rowptr[w], s1 = rowptr[w + 1];
    float4 iv = inv[w];
    float ia = (lane < 16) ? iv.x : iv.y;
    float ib = (lane < 16) ? iv.z : iv.w;

    float4 a0 = make_float4(0, 0, 0, 0), a1 = make_float4(0, 0, 0, 0);
    const float4* fp = reinterpret_cast<const float4*>(fs);
    int e = s0;
    for (; e + 4 <= s1; e += 4) {
        int sA = srcs[e], sB = srcs[e + 1], sC = srcs[e + 2], sD = srcs[e + 3];
        float4 wA = ew[e], wB = ew[e + 1], wC = ew[e + 2], wD = ew[e + 3];
        const float4* pA = fp + (size_t)sA * 64 + lane;
        const float4* pB = fp + (size_t)sB * 64 + lane;
        const float4* pC = fp + (size_t)sC * 64 + lane;
        const float4* pD = fp + (size_t)sD * 64 + lane;
        float4 fA0 = pA[0], fA1 = pA[32];
        float4 fB0 = pB[0], fB1 = pB[32];
        float4 fC0 = pC[0], fC1 = pC[32];
        float4 fD0 = pD[0], fD1 = pD[32];
        float wa, wb;
        wa = ((lane < 16) ? wA.x : wA.y) * ia; wb = ((lane < 16) ? wA.z : wA.w) * ib;
        a0.x = fmaf(wa, fA0.x, a0.x); a0.y = fmaf(wa, fA0.y, a0.y);
        a0.z = fmaf(wa, fA0.z, a0.z); a0.w = fmaf(wa, fA0.w, a0.w);
        a1.x = fmaf(wb, fA1.x, a1.x); a1.y = fmaf(wb, fA1.y, a1.y);
        a1.z = fmaf(wb, fA1.z, a1.z); a1.w = fmaf(wb, fA1.w, a1.w);
        wa = ((lane < 16) ? wB.x : wB.y) * ia; wb = ((lane < 16) ? wB.z : wB.w) * ib;
        a0.x = fmaf(wa, fB0.x, a0.x); a0.y = fmaf(wa, fB0.y, a0.y);
        a0.z = fmaf(wa, fB0.z, a0.z); a0.w = fmaf(wa, fB0.w, a0.w);
        a1.x = fmaf(wb, fB1.x, a1.x); a1.y = fmaf(wb, fB1.y, a1.y);
        a1.z = fmaf(wb, fB1.z, a1.z); a1.w = fmaf(wb, fB1.w, a1.w);
        wa = ((lane < 16) ? wC.x : wC.y) * ia; wb = ((lane < 16) ? wC.z : wC.w) * ib;
        a0.x = fmaf(wa, fC0.x, a0.x); a0.y = fmaf(wa, fC0.y, a0.y);
        a0.z = fmaf(wa, fC0.z, a0.z); a0.w = fmaf(wa, fC0.w, a0.w);
        a1.x = fmaf(wb, fC1.x, a1.x); a1.y = fmaf(wb, fC1.y, a1.y);
        a1.z = fmaf(wb, fC1.z, a1.z); a1.w = fmaf(wb, fC1.w, a1.w);
        wa = ((lane < 16) ? wD.x : wD.y) * ia; wb = ((lane < 16) ? wD.z : wD.w) * ib;
        a0.x = fmaf(wa, fD0.x, a0.x); a0.y = fmaf(wa, fD0.y, a0.y);
        a0.z = fmaf(wa, fD0.z, a0.z); a0.w = fmaf(wa, fD0.w, a0.w);
        a1.x = fmaf(wb, fD1.x, a1.x); a1.y = fmaf(wb, fD1.y, a1.y);
        a1.z = fmaf(wb, fD1.z, a1.z); a1.w = fmaf(wb, fD1.w, a1.w);
    }
    for (; e < s1; e++) {
        int s = srcs[e];
        float4 w4 = ew[e];
        float wa = ((lane < 16) ? w4.x : w4.y) * ia;
        float wb = ((lane < 16) ? w4.z : w4.w) * ib;
        float4 f0 = fp[(size_t)s * 64 + lane];
        float4 f1 = fp[(size_t)s * 64 + 32 + lane];
        a0.x = fmaf(wa, f0.x, a0.x); a0.y = fmaf(wa, f0.y, a0.y);
        a0.z = fmaf(wa, f0.z, a0.z); a0.w = fmaf(wa, f0.w, a0.w);
        a1.x = fmaf(wb, f1.x, a1.x); a1.y = fmaf(wb, f1.y, a1.y);
        a1.z = fmaf(wb, f1.z, a1.z); a1.w = fmaf(wb, f1.w, a1.w);
    }
    const float4* rp = reinterpret_cast<const float4*>(resid);
    float4 r0 = rp[(size_t)w * 64 + lane];
    float4 r1 = rp[(size_t)w * 64 + 32 + lane];
    float4 o0, o1;
    o0.x = eluf(a0.x + r0.x); o0.y = eluf(a0.y + r0.y);
    o0.z = eluf(a0.z + r0.z); o0.w = eluf(a0.w + r0.w);
    o1.x = eluf(a1.x + r1.x); o1.y = eluf(a1.y + r1.y);
    o1.z = eluf(a1.z + r1.z); o1.w = eluf(a1.w + r1.w);
    float4* op = reinterpret_cast<float4*>(out);
    op[(size_t)w * 64 + lane] = o0;
    op[(size_t)w * 64 + 32 + lane] = o1;
}

// L2: gather + residual + head-mean fused -> out [n,32]
__global__ void k_gather2fin(const int* __restrict__ rowptr, const int* __restrict__ srcs,
                             const float* __restrict__ fs, const float* __restrict__ resid,
                             const float4* __restrict__ inv, const float4* __restrict__ ew,
                             float* __restrict__ out, int n) {
    int w = (blockIdx.x * blockDim.x + threadIdx.x) >> 5;
    if (w >= n) return;
    int lane = threadIdx.x & 31;
    int s0 = rowptr[w], s1 = rowptr[w + 1];
    float4 iv = inv[w];
    int hsel = lane >> 3;
    float isel = (hsel < 2) ? (hsel ? iv.y : iv.x) : (hsel == 2 ? iv.z : iv.w);

    float4 a0 = make_float4(0, 0, 0, 0);
    const float4* fp = reinterpret_cast<const float4*>(fs);
    int e = s0;
    for (; e + 4 <= s1; e += 4) {
        int sA = srcs[e], sB = srcs[e + 1], sC = srcs[e + 2], sD = srcs[e + 3];
        float4 wA = ew[e], wB = ew[e + 1], wC = ew[e + 2], wD = ew[e + 3];
        float4 fA = fp[(size_t)sA * 32 + lane];
        float4 fB = fp[(size_t)sB * 32 + lane];
        float4 fC = fp[(size_t)sC * 32 + lane];
        float4 fD = fp[(size_t)sD * 32 + lane];
        float wa;
        wa = ((hsel < 2) ? (hsel ? wA.y : wA.x) : (hsel == 2 ? wA.z : wA.w)) * isel;
        a0.x = fmaf(wa, fA.x, a0.x); a0.y = fmaf(wa, fA.y, a0.y);
        a0.z = fmaf(wa, fA.z, a0.z); a0.w = fmaf(wa, fA.w, a0.w);
        wa = ((hsel < 2) ? (hsel ? wB.y : wB.x) : (hsel == 2 ? wB.z : wB.w)) * isel;
        a0.x = fmaf(wa, fB.x, a0.x); a0.y = fmaf(wa, fB.y, a0.y);
        a0.z = fmaf(wa, fB.z, a0.z); a0.w = fmaf(wa, fB.w, a0.w);
        wa = ((hsel < 2) ? (hsel ? wC.y : wC.x) : (hsel == 2 ? wC.z : wC.w)) * isel;
        a0.x = fmaf(wa, fC.x, a0.x); a0.y = fmaf(wa, fC.y, a0.y);
        a0.z = fmaf(wa, fC.z, a0.z); a0.w = fmaf(wa, fC.w, a0.w);
        wa = ((hsel < 2) ? (hsel ? wD.y : wD.x) : (hsel == 2 ? wD.z : wD.w)) * isel;
        a0.x = fmaf(wa, fD.x, a0.x); a0.y = fmaf(wa, fD.y, a0.y);
        a0.z = fmaf(wa, fD.z, a0.z); a0.w = fmaf(wa, fD.w, a0.w);
    }
    for (; e < s1; e++) {
        int s = srcs[e];
        float4 w4 = ew[e];
        float wa = ((hsel < 2) ? (hsel ? w4.y : w4.x) : (hsel == 2 ? w4.z : w4.w)) * isel;
        float4 f0 = fp[(size_t)s * 32 + lane];
        a0.x = fmaf(wa, f0.x, a0.x); a0.y = fmaf(wa, f0.y, a0.y);
        a0.z = fmaf(wa, f0.z, a0.z); a0.w = fmaf(wa, f0.w, a0.w);
    }
    const float4* rp = reinterpret_cast<const float4*>(resid);
    float4 r = rp[(size_t)w * 32 + lane];
    float4 v;
    v.x = a0.x + r.x; v.y = a0.y + r.y; v.z = a0.z + r.z; v.w = a0.w + r.w;
    // mean over heads: lanes L, L^8, L^16, L^24 hold same output channels
    v.x += __shfl_xor_sync(0xffffffffu, v.x, 8);
    v.y += __shfl_xor_sync(0xffffffffu, v.y, 8);
    v.z += __shfl_xor_sync(0xffffffffu, v.z, 8);
    v.w += __shfl_xor_sync(0xffffffffu, v.w, 8);
    v.x += __shfl_xor_sync(0xffffffffu, v.x, 16);
    v.y += __shfl_xor_sync(0xffffffffu, v.y, 16);
    v.z += __shfl_xor_sync(0xffffffffu, v.z, 16);
    v.w += __shfl_xor_sync(0xffffffffu, v.w, 16);
    if (lane < 8) {
        v.x *= 0.25f; v.y *= 0.25f; v.z *= 0.25f; v.w *= 0.25f;
        reinterpret_cast<float4*>(out)[(size_t)w * 8 + lane] = v;
    }
}

// ---------------- launcher with fork/join overlap ----------------
extern "C" void kernel_launch(void* const* d_in, const int* in_sizes, int n_in,
                              void* d_out, int out_size) {
    const float* h   = (const float*)d_in[0];
    const int*   src = (const int*)d_in[1];
    const int*   dst = (const int*)d_in[2];
    const float* W1s = (const float*)d_in[3];
    const float* W1d = (const float*)d_in[4];
    const float* al1 = (const float*)d_in[5];
    const float* ar1 = (const float*)d_in[6];
    const float* W2s = (const float*)d_in[7];
    const float* W2d = (const float*)d_in[8];
    const float* al2 = (const float*)d_in[9];
    const float* ar2 = (const float*)d_in[10];
    const float* Wr2 = (const float*)d_in[11];
    float* out = (float*)d_out;

    int Nn = in_sizes[0] / 256;
    int E  = in_sizes[1];
    if (Nn > NMAX) Nn = NMAX;
    if (E  > EMAX) E  = EMAX;

    float *fs1, *h1, *fs2, *res2, *VU1, *VU2;
    float4 *el1, *er1, *el2, *er2, *ew1, *ew2, *inv1, *inv2;
    int *rowptr, *cursor, *deg, *srcs, *bsum;
    cudaGetSymbolAddress((void**)&fs1,    g_fs1);
    cudaGetSymbolAddress((void**)&h1,     g_h1);
    cudaGetSymbolAddress((void**)&fs2,    g_fs2);
    cudaGetSymbolAddress((void**)&res2,   g_res2);
    cudaGetSymbolAddress((void**)&VU1,    g_VU1);
    cudaGetSymbolAddress((void**)&VU2,    g_VU2);
    cudaGetSymbolAddress((void**)&el1,    g_el1);
    cudaGetSymbolAddress((void**)&er1,    g_er1);
    cudaGetSymbolAddress((void**)&el2,    g_el2);
    cudaGetSymbolAddress((void**)&er2,    g_er2);
    cudaGetSymbolAddress((void**)&ew1,    g_ew1);
    cudaGetSymbolAddress((void**)&ew2,    g_ew2);
    cudaGetSymbolAddress((void**)&inv1,   g_inv1);
    cudaGetSymbolAddress((void**)&inv2,   g_inv2);
    cudaGetSymbolAddress((void**)&rowptr, g_rowptr);
    cudaGetSymbolAddress((void**)&cursor, g_cursor);
    cudaGetSymbolAddress((void**)&deg,    g_deg);
    cudaGetSymbolAddress((void**)&srcs,   g_srcs);
    cudaGetSymbolAddress((void**)&bsum,   g_bsum);

    cudaFuncSetAttribute(k_gemm<256, false>, cudaFuncAttributeMaxDynamicSharedMemorySize, GEMM_SMEM);
    cudaFuncSetAttribute(k_gemm<128, true >, cudaFuncAttributeMaxDynamicSharedMemorySize, GEMM_SMEM);

    int wblocks = (Nn * 32 + 255) / 256;
    int nch = (Nn + 1023) / 1024;
    dim3 g1((Nn + 127) / 128, 4);   // N=256 in 64-wide tiles
    dim3 g2((Nn + 127) / 128, 4);   // two N=128 matrices, 2 tiles each

    cudaStream_t side;
    cudaStreamCreateWithFlags(&side, cudaStreamNonBlocking);
    cudaEvent_t evFork1, evJoin1, evFork2, evJoin2;
    cudaEventCreateWithFlags(&evFork1, cudaEventDisableTiming);
    cudaEventCreateWithFlags(&evJoin1, cudaEventDisableTiming);
    cudaEventCreateWithFlags(&evFork2, cudaEventDisableTiming);
    cudaEventCreateWithFlags(&evJoin2, cudaEventDisableTiming);

    // ---- fork 1: CSR + eler1 + soft1 on side; GEMM1 on main ----
    cudaEventRecord(evFork1, 0);
    cudaStreamWaitEvent(side, evFork1, 0);

    k_zero<<<(Nn + 255) / 256, 256, 0, side>>>(deg, Nn);
    k_hist<<<(E + 255) / 256, 256, 0, side>>>(dst, deg, E);
    k_scan_chunk<<<nch, 1024, 0, side>>>(deg, rowptr, bsum, Nn);
    k_scan_add<<<(Nn + 255) / 256, 256, 0, side>>>(rowptr, cursor, bsum, Nn, E, nch);
    k_scatter<<<(E + 255) / 256, 256, 0, side>>>(src, dst, cursor, srcs, E);
    k_vecs<64><<<8, 256, 0, side>>>(W1s, al1, W1d, ar1, VU1);
    k_eler<<<wblocks, 256, 0, side>>>(h, VU1, el1, er1, Nn);
    k_soft<<<wblocks, 256, 0, side>>>(rowptr, srcs, el1, er1, ew1, inv1, Nn);
    cudaEventRecord(evJoin1, side);

    k_gemm<256, false><<<g1, 256, GEMM_SMEM>>>(h, W1s, nullptr, fs1, nullptr, Nn);

    cudaStreamWaitEvent(0, evJoin1, 0);
    k_gather1<<<wblocks, 256>>>(rowptr, srcs, fs1, h, inv1, ew1, h1, Nn);

    // ---- fork 2: eler2 + soft2 on side; combined GEMM2 (fs2 + res2) on main ----
    cudaEventRecord(evFork2, 0);
    cudaStreamWaitEvent(side, evFork2, 0);

    k_vecs<32><<<8, 256, 0, side>>>(W2s, al2, W2d, ar2, VU2);
    k_eler<<<wblocks, 256, 0, side>>>(h1, VU2, el2, er2, Nn);
    k_soft<<<wblocks, 256, 0, side>>>(rowptr, srcs, el2, er2, ew2, inv2, Nn);
    cudaEventRecord(evJoin2, side);

    k_gemm<128, true><<<g2, 256, GEMM_SMEM>>>(h1, W2s, Wr2, fs2, res2, Nn);

    cudaStreamWaitEvent(0, evJoin2, 0);
    k_gather2fin<<<wblocks, 256>>>(rowptr, srcs, fs2, res2, inv2, ew2, out, Nn);
}

// round 14
// speedup vs baseline: 1.2294x; 1.1967x over previous
#include <cuda_runtime.h>
#include <cuda_fp16.h>
#include <cstdint>
#include <mma.h>

using namespace nvcuda;

#define NMAX 50000
#define EMAX 850000

// ---------------- scratch (device globals; no allocation allowed) ----------------
__device__ float  g_fs1[(size_t)NMAX * 256];
__device__ float  g_h1 [(size_t)NMAX * 256];
__device__ float  g_fs2[(size_t)NMAX * 128];
__device__ float  g_res2[(size_t)NMAX * 128];
__device__ __half g_h16 [(size_t)NMAX * 256];
__device__ __half g_w1s16[256 * 256];
__device__ float4 g_ew [EMAX];
__device__ float4 g_el1[NMAX];
__device__ float4 g_er1[NMAX];
__device__ float4 g_el2[NMAX];
__device__ float4 g_er2[NMAX];
__device__ int    g_rowptr[NMAX + 1];
__device__ int    g_cursor[NMAX];
__device__ int    g_deg[NMAX];
__device__ int    g_srcs[EMAX];
__device__ float  g_VU1[8 * 256];
__device__ float  g_VU2[8 * 256];
__device__ int    g_bsum[128];

__device__ __forceinline__ float lrelu(float x) { return x > 0.f ? x : 0.2f * x; }
__device__ __forceinline__ float eluf (float x) { return x > 0.f ? x : expm1f(x); }

__device__ __forceinline__ void cpa16(void* s, const void* g, bool pred) {
    unsigned int sa = (unsigned int)__cvta_generic_to_shared(s);
    int sz = pred ? 16 : 0;
    asm volatile("cp.async.cg.shared.global [%0], [%1], 16, %2;\n" :: "r"(sa), "l"(g), "r"(sz));
}
__device__ __forceinline__ void cpa_commit() { asm volatile("cp.async.commit_group;\n"); }

// ---------------- fp32 -> fp16 conversion (vectorized) ----------------
__global__ void k_cvt(const float* __restrict__ in, __half* __restrict__ out, int n4) {
    int i = blockIdx.x * blockDim.x + threadIdx.x;
    if (i < n4) {
        float4 v = reinterpret_cast<const float4*>(in)[i];
        __half2* o = reinterpret_cast<__half2*>(out) + i * 2;
        o[0] = __floats2half2_rn(v.x, v.y);
        o[1] = __floats2half2_rn(v.z, v.w);
    }
}

// ---------------- CSR build ----------------
__global__ void k_zero(int* __restrict__ deg, int n) {
    int i = blockIdx.x * blockDim.x + threadIdx.x;
    if (i < n) deg[i] = 0;
}

__global__ void k_hist(const int* __restrict__ dst, int* __restrict__ deg, int E) {
    int i = blockIdx.x * blockDim.x + threadIdx.x;
    if (i < E) atomicAdd(&deg[dst[i]], 1);
}

__global__ void k_scan_chunk(const int* __restrict__ deg, int* __restrict__ rowptr,
                             int* __restrict__ bsum, int n) {
    __shared__ int sm[1024];
    int b = blockIdx.x, t = threadIdx.x;
    int i = b * 1024 + t;
    int x = (i < n) ? deg[i] : 0;
    sm[t] = x;
    __syncthreads();
    for (int off = 1; off < 1024; off <<= 1) {
        int v = (t >= off) ? sm[t - off] : 0;
        __syncthreads();
        sm[t] += v;
        __syncthreads();
    }
    if (i < n) rowptr[i] = sm[t] - x;
    if (t == 1023) bsum[b] = sm[1023];
}

__global__ void k_scan_add(int* __restrict__ rowptr, int* __restrict__ cursor,
                           const int* __restrict__ bsum, int n, int E, int nch) {
    __shared__ int sb[64];
    if (threadIdx.x < 64) sb[threadIdx.x] = (threadIdx.x < nch) ? bsum[threadIdx.x] : 0;
    __syncthreads();
    int i = blockIdx.x * blockDim.x + threadIdx.x;
    if (i < n) {
        int ch = i >> 10, off = 0;
        for (int j = 0; j < ch; j++) off += sb[j];
        int v = rowptr[i] + off;
        rowptr[i] = v;
        cursor[i] = v;
        if (i == 0) rowptr[n] = E;
    }
}

__global__ void k_scatter(const int* __restrict__ src, const int* __restrict__ dst,
                          int* __restrict__ cursor, int* __restrict__ srcs, int E) {
    int i = blockIdx.x * blockDim.x + threadIdx.x;
    if (i < E) {
        int d = dst[i];
        int pos = atomicAdd(&cursor[d], 1);
        srcs[pos] = src[i];
    }
}

// ---------------- attention-score projection vectors ----------------
template <int DHH>
__global__ void k_vecs(const float* __restrict__ Ws, const float* __restrict__ al,
                       const float* __restrict__ Wd, const float* __restrict__ ar,
                       float* __restrict__ out) {
    int id = blockIdx.x * blockDim.x + threadIdx.x;
    if (id >= 256 * 8) return;
    int i = id >> 3, j = id & 7, h = j & 3;
    const float* W = (j < 4) ? Ws : Wd;
    const float* a = (j < 4) ? al : ar;
    float s = 0.f;
#pragma unroll 4
    for (int d = 0; d < DHH; d++) s += W[i * (4 * DHH) + h * DHH + d] * a[h * DHH + d];
    out[j * 256 + i] = s;
}

// el/er for every node: warp per node, X is [n,256]
__global__ void k_eler(const float* __restrict__ X, const float* __restrict__ VU,
                       float4* __restrict__ el, float4* __restrict__ er, int n) {
    __shared__ float sVU[8 * 256];
    for (int i = threadIdx.x; i < 8 * 256; i += blockDim.x) sVU[i] = VU[i];
    __syncthreads();
    int w = (blockIdx.x * blockDim.x + threadIdx.x) >> 5;
    int lane = threadIdx.x & 31;
    if (w >= n) return;
    const float* x = X + (size_t)w * 256;
    float acc[8] = {0, 0, 0, 0, 0, 0, 0, 0};
#pragma unroll
    for (int k = 0; k < 8; k++) {
        int idx = lane + 32 * k;
        float v = x[idx];
#pragma unroll
        for (int j = 0; j < 8; j++) acc[j] = fmaf(v, sVU[j * 256 + idx], acc[j]);
    }
#pragma unroll
    for (int off = 16; off; off >>= 1)
#pragma unroll
        for (int j = 0; j < 8; j++) acc[j] += __shfl_xor_sync(0xffffffffu, acc[j], off);
    if (lane == 0) {
        el[w] = make_float4(acc[0], acc[1], acc[2], acc[3]);
        er[w] = make_float4(acc[4], acc[5], acc[6], acc[7]);
    }
}

// ---------------- fp16 WMMA GEMM (layer-1 only): C = A[M,256] * B[256,256] ----------------
// CTA tile 128x64, 8 warps 4m x 2n, K chunks of 32 (2 mma-K steps). A,B fp16; accum/C fp32.
#define SMA16_ST (128 * 40)
#define SMB16_ST (32 * 72)
#define GEMM16_SMEM (3 * (SMA16_ST + SMB16_ST) * 2)

__global__ void __launch_bounds__(256, 2) k_gemm16(const __half* __restrict__ A,
                                                   const __half* __restrict__ B,
                                                   float* __restrict__ C, int M) {
    extern __shared__ __half smh[];
    const int NCOLS = 256;
    int colBase = blockIdx.y * 64;
    int rowBase = blockIdx.x * 128;
    int tid = threadIdx.x, lane = tid & 31, warp = tid >> 5;
    int wm = warp & 3, wn = warp >> 2;

    wmma::fragment<wmma::accumulator, 16, 16, 16, float> acc[2][2];
#pragma unroll
    for (int i = 0; i < 2; i++)
#pragma unroll
        for (int j = 0; j < 2; j++) wmma::fill_fragment(acc[i][j], 0.0f);

    auto loadTile = [&](int it) {
        int stage = it % 3;
        int k0 = it * 32;
        __half* As = smh + stage * (SMA16_ST + SMB16_ST);
        __half* Bs = As + SMA16_ST;
#pragma unroll
        for (int i = 0; i < 2; i++) {            // A: 128 rows x 4 chunks(8 halves)
            int idx = i * 256 + tid;
            int r = idx >> 2, c8 = idx & 3;
            int gr = rowBase + r;
            int grc = (gr < M) ? gr : (M - 1);
            cpa16(&As[r * 40 + c8 * 8], &A[(size_t)grc * 256 + k0 + c8 * 8], gr < M);
        }
        {                                        // B: 32 rows x 8 chunks
            int r = tid >> 3, c8 = tid & 7;
            cpa16(&Bs[r * 72 + c8 * 8], &B[(size_t)(k0 + r) * NCOLS + colBase + c8 * 8], true);
        }
    };

    loadTile(0); cpa_commit();
    loadTile(1); cpa_commit();

#pragma unroll 1
    for (int it = 0; it < 8; it++) {
        asm volatile("cp.async.wait_group 1;\n");
        __syncthreads();
        if (it + 2 < 8) { loadTile(it + 2); cpa_commit(); }
        const __half* As = smh + (it % 3) * (SMA16_ST + SMB16_ST);
        const __half* Bs = As + SMA16_ST;
#pragma unroll
        for (int kk = 0; kk < 32; kk += 16) {
            wmma::fragment<wmma::matrix_b, 16, 16, 16, __half, wmma::row_major> bf[2];
#pragma unroll
            for (int j = 0; j < 2; j++)
                wmma::load_matrix_sync(bf[j], Bs + kk * 72 + wn * 32 + j * 16, 72);
#pragma unroll
            for (int i = 0; i < 2; i++) {
                wmma::fragment<wmma::matrix_a, 16, 16, 16, __half, wmma::row_major> af;
                wmma::load_matrix_sync(af, As + (wm * 32 + i * 16) * 40 + kk, 40);
#pragma unroll
                for (int j = 0; j < 2; j++) wmma::mma_sync(acc[i][j], af, bf[j], acc[i][j]);
            }
        }
    }
    asm volatile("cp.async.wait_group 0;\n");
    __syncthreads();

    float* stgbase = reinterpret_cast<float*>(smh);
#pragma unroll
    for (int i = 0; i < 2; i++) {
        int r0 = rowBase + wm * 32 + i * 16;
#pragma unroll
        for (int j = 0; j < 2; j++) {
            int c0 = colBase + wn * 32 + j * 16;
            if (r0 + 16 <= M) {
                wmma::store_matrix_sync(&C[(size_t)r0 * NCOLS + c0], acc[i][j], NCOLS, wmma::mem_row_major);
            } else if (r0 < M) {
                float* stg = stgbase + warp * 320;
                wmma::store_matrix_sync(stg, acc[i][j], 20, wmma::mem_row_major);
                __syncwarp();
                for (int idx = lane; idx < 256; idx += 32) {
                    int rr = idx >> 4, cc = idx & 15;
                    if (r0 + rr < M) C[(size_t)(r0 + rr) * NCOLS + c0 + cc] = stg[rr * 20 + cc];
                }
                __syncwarp();
            }
        }
    }
}

// ---------------- tf32 WMMA GEMM (layer 2, DUAL), 3-stage cp.async (R9) ----------------
#define SMA_ST (128 * 36)
#define SMB_ST (32 * 68)
#define GEMM_SMEM (3 * (SMA_ST + SMB_ST) * 4)

template <int NCOLS, bool DUAL>
__global__ void __launch_bounds__(256, 2) k_gemm(const float* __restrict__ A,
                                                 const float* __restrict__ B0,
                                                 const float* __restrict__ B1,
                                                 float* __restrict__ C0,
                                                 float* __restrict__ C1, int M) {
    extern __shared__ float smx[];
    constexpr int TPG = NCOLS / 64;
    const float* B = (DUAL && (blockIdx.y >= TPG)) ? B1 : B0;
    float* C = (DUAL && (blockIdx.y >= TPG)) ? C1 : C0;
    int colBase = (DUAL ? (blockIdx.y % TPG) : blockIdx.y) * 64;
    int rowBase = blockIdx.x * 128;
    int tid = threadIdx.x, lane = tid & 31, warp = tid >> 5;
    int wm = warp & 3, wn = warp >> 2;

    wmma::fragment<wmma::accumulator, 16, 16, 8, float> acc[2][2];
#pragma unroll
    for (int i = 0; i < 2; i++)
#pragma unroll
        for (int j = 0; j < 2; j++) wmma::fill_fragment(acc[i][j], 0.0f);

    auto loadTile = [&](int it) {
        int stage = it % 3;
        int k0 = it * 32;
        float* As = smx + stage * (SMA_ST + SMB_ST);
        float* Bs = As + SMA_ST;
#pragma unroll
        for (int i = 0; i < 4; i++) {
            int f4 = i * 256 + tid;
            int r = f4 >> 3, c4 = f4 & 7;
            int gr = rowBase + r;
            int grc = (gr < M) ? gr : (M - 1);
            cpa16(&As[r * 36 + c4 * 4], &A[(size_t)grc * 256 + k0 + c4 * 4], gr < M);
        }
#pragma unroll
        for (int i = 0; i < 2; i++) {
            int f4 = i * 256 + tid;
            int r = f4 >> 4, c4 = f4 & 15;
            cpa16(&Bs[r * 68 + c4 * 4], &B[(size_t)(k0 + r) * NCOLS + colBase + c4 * 4], true);
        }
    };

    loadTile(0); cpa_commit();
    loadTile(1); cpa_commit();

#pragma unroll 1
    for (int it = 0; it < 8; it++) {
        asm volatile("cp.async.wait_group 1;\n");
        __syncthreads();
        if (it + 2 < 8) { loadTile(it + 2); cpa_commit(); }
        const float* As = smx + (it % 3) * (SMA_ST + SMB_ST);
        const float* Bs = As + SMA_ST;
#pragma unroll
        for (int kk = 0; kk < 32; kk += 8) {
            wmma::fragment<wmma::matrix_b, 16, 16, 8, wmma::precision::tf32, wmma::row_major> bf[2];
#pragma unroll
            for (int j = 0; j < 2; j++) {
                wmma::load_matrix_sync(bf[j], Bs + kk * 68 + wn * 32 + j * 16, 68);
#pragma unroll
                for (int t = 0; t < bf[j].num_elements; t++)
                    bf[j].x[t] = wmma::__float_to_tf32(bf[j].x[t]);
            }
#pragma unroll
            for (int i = 0; i < 2; i++) {
                wmma::fragment<wmma::matrix_a, 16, 16, 8, wmma::precision::tf32, wmma::row_major> af;
                wmma::load_matrix_sync(af, As + (wm * 32 + i * 16) * 36 + kk, 36);
#pragma unroll
                for (int t = 0; t < af.num_elements; t++)
                    af.x[t] = wmma::__float_to_tf32(af.x[t]);
#pragma unroll
                for (int j = 0; j < 2; j++) wmma::mma_sync(acc[i][j], af, bf[j], acc[i][j]);
            }
        }
    }
    asm volatile("cp.async.wait_group 0;\n");
    __syncthreads();

#pragma unroll
    for (int i = 0; i < 2; i++) {
        int r0 = rowBase + wm * 32 + i * 16;
#pragma unroll
        for (int j = 0; j < 2; j++) {
            int c0 = colBase + wn * 32 + j * 16;
            if (r0 + 16 <= M) {
                wmma::store_matrix_sync(&C[(size_t)r0 * NCOLS + c0], acc[i][j], NCOLS, wmma::mem_row_major);
            } else if (r0 < M) {
                float* stg = smx + warp * 320;
                wmma::store_matrix_sync(stg, acc[i][j], 20, wmma::mem_row_major);
                __syncwarp();
                for (int idx = lane; idx < 256; idx += 32) {
                    int rr = idx >> 4, cc = idx & 15;
                    if (r0 + rr < M) C[(size_t)(r0 + rr) * NCOLS + c0 + cc] = stg[rr * 20 + cc];
                }
                __syncwarp();
            }
        }
    }
}

// ---------------- fused segment-softmax + weighted aggregation (R9) ----------------
template <bool L1>
__global__ void k_agg(const int* __restrict__ rowptr, const int* __restrict__ srcs,
                      const float4* __restrict__ el, const float4* __restrict__ er,
                      const float* __restrict__ fs, const float* __restrict__ resid,
                      float* __restrict__ out, float4* __restrict__ ew, int n) {
    int w = (blockIdx.x * blockDim.x + threadIdx.x) >> 5;
    if (w >= n) return;
    int lane = threadIdx.x & 31;
    int s0 = rowptr[w], s1 = rowptr[w + 1];
    float4 erv = er[w];

    float m0 = -1e30f, m1 = -1e30f, m2 = -1e30f, m3 = -1e30f;
    for (int e = s0 + lane; e < s1; e += 32) {
        float4 ev = el[srcs[e]];
        m0 = fmaxf(m0, lrelu(ev.x + erv.x));
        m1 = fmaxf(m1, lrelu(ev.y + erv.y));
        m2 = fmaxf(m2, lrelu(ev.z + erv.z));
        m3 = fmaxf(m3, lrelu(ev.w + erv.w));
    }
#pragma unroll
    for (int off = 16; off; off >>= 1) {
        m0 = fmaxf(m0, __shfl_xor_sync(0xffffffffu, m0, off));
        m1 = fmaxf(m1, __shfl_xor_sync(0xffffffffu, m1, off));
        m2 = fmaxf(m2, __shfl_xor_sync(0xffffffffu, m2, off));
        m3 = fmaxf(m3, __shfl_xor_sync(0xffffffffu, m3, off));
    }
    float t0 = 0.f, t1 = 0.f, t2 = 0.f, t3 = 0.f;
    for (int e = s0 + lane; e < s1; e += 32) {
        float4 ev = el[srcs[e]];
        float4 x;
        x.x = __expf(lrelu(ev.x + erv.x) - m0);
        x.y = __expf(lrelu(ev.y + erv.y) - m1);
        x.z = __expf(lrelu(ev.z + erv.z) - m2);
        x.w = __expf(lrelu(ev.w + erv.w) - m3);
        ew[e] = x;
        t0 += x.x; t1 += x.y; t2 += x.z; t3 += x.w;
    }
#pragma unroll
    for (int off = 16; off; off >>= 1) {
        t0 += __shfl_xor_sync(0xffffffffu, t0, off);
        t1 += __shfl_xor_sync(0xffffffffu, t1, off);
        t2 += __shfl_xor_sync(0xffffffffu, t2, off);
        t3 += __shfl_xor_sync(0xffffffffu, t3, off);
    }
    float i0 = 1.f / t0, i1 = 1.f / t1, i2 = 1.f / t2, i3 = 1.f / t3;
    __syncwarp();

    if (L1) {
        float ia = (lane < 16) ? i0 : i1;
        float ib = (lane < 16) ? i2 : i3;
        float4 a0 = make_float4(0, 0, 0, 0), a1 = make_float4(0, 0, 0, 0);
        const float4* fp = reinterpret_cast<const float4*>(fs);
        int e = s0;
        for (; e + 4 <= s1; e += 4) {
            int sA = srcs[e], sB = srcs[e + 1], sC = srcs[e + 2], sD = srcs[e + 3];
            float4 wA = ew[e], wB = ew[e + 1], wC = ew[e + 2], wD = ew[e + 3];
            const float4* pA = fp + (size_t)sA * 64 + lane;
            const float4* pB = fp + (size_t)sB * 64 + lane;
            const float4* pC = fp + (size_t)sC * 64 + lane;
            const float4* pD = fp + (size_t)sD * 64 + lane;
            float4 fA0 = pA[0], fA1 = pA[32];
            float4 fB0 = pB[0], fB1 = pB[32];
            float4 fC0 = pC[0], fC1 = pC[32];
            float4 fD0 = pD[0], fD1 = pD[32];
            float wa, wb;
            wa = ((lane < 16) ? wA.x : wA.y) * ia; wb = ((lane < 16) ? wA.z : wA.w) * ib;
            a0.x = fmaf(wa, fA0.x, a0.x); a0.y = fmaf(wa, fA0.y, a0.y);
            a0.z = fmaf(wa, fA0.z, a0.z); a0.w = fmaf(wa, fA0.w, a0.w);
            a1.x = fmaf(wb, fA1.x, a1.x); a1.y = fmaf(wb, fA1.y, a1.y);
            a1.z = fmaf(wb, fA1.z, a1.z); a1.w = fmaf(wb, fA1.w, a1.w);
            wa = ((lane < 16) ? wB.x : wB.y) * ia; wb = ((lane < 16) ? wB.z : wB.w) * ib;
            a0.x = fmaf(wa, fB0.x, a0.x); a0.y = fmaf(wa, fB0.y, a0.y);
            a0.z = fmaf(wa, fB0.z, a0.z); a0.w = fmaf(wa, fB0.w, a0.w);
            a1.x = fmaf(wb, fB1.x, a1.x); a1.y = fmaf(wb, fB1.y, a1.y);
            a1.z = fmaf(wb, fB1.z, a1.z); a1.w = fmaf(wb, fB1.w, a1.w);
            wa = ((lane < 16) ? wC.x : wC.y) * ia; wb = ((lane < 16) ? wC.z : wC.w) * ib;
            a0.x = fmaf(wa, fC0.x, a0.x); a0.y = fmaf(wa, fC0.y, a0.y);
            a0.z = fmaf(wa, fC0.z, a0.z); a0.w = fmaf(wa, fC0.w, a0.w);
            a1.x = fmaf(wb, fC1.x, a1.x); a1.y = fmaf(wb, fC1.y, a1.y);
            a1.z = fmaf(wb, fC1.z, a1.z); a1.w = fmaf(wb, fC1.w, a1.w);
            wa = ((lane < 16) ? wD.x : wD.y) * ia; wb = ((lane < 16) ? wD.z : wD.w) * ib;
            a0.x = fmaf(wa, fD0.x, a0.x); a0.y = fmaf(wa, fD0.y, a0.y);
            a0.z = fmaf(wa, fD0.z, a0.z); a0.w = fmaf(wa, fD0.w, a0.w);
            a1.x = fmaf(wb, fD1.x, a1.x); a1.y = fmaf(wb, fD1.y, a1.y);
            a1.z = fmaf(wb, fD1.z, a1.z); a1.w = fmaf(wb, fD1.w, a1.w);
        }
        for (; e < s1; e++) {
            int s = srcs[e];
            float4 w4 = ew[e];
            float wa = ((lane < 16) ? w4.x : w4.y) * ia;
            float wb = ((lane < 16) ? w4.z : w4.w) * ib;
            float4 f0 = fp[(size_t)s * 64 + lane];
            float4 f1 = fp[(size_t)s * 64 + 32 + lane];
            a0.x = fmaf(wa, f0.x, a0.x); a0.y = fmaf(wa, f0.y, a0.y);
            a0.z = fmaf(wa, f0.z, a0.z); a0.w = fmaf(wa, f0.w, a0.w);
            a1.x = fmaf(wb, f1.x, a1.x); a1.y = fmaf(wb, f1.y, a1.y);
            a1.z = fmaf(wb, f1.z, a1.z); a1.w = fmaf(wb, f1.w, a1.w);
        }
        const float4* rp = reinterpret_cast<const float4*>(resid);
        float4 r0 = rp[(size_t)w * 64 + lane];
        float4 r1 = rp[(size_t)w * 64 + 32 + lane];
        float4 o0, o1;
        o0.x = eluf(a0.x + r0.x); o0.y = eluf(a0.y + r0.y);
        o0.z = eluf(a0.z + r0.z); o0.w = eluf(a0.w + r0.w);
        o1.x = eluf(a1.x + r1.x); o1.y = eluf(a1.y + r1.y);
        o1.z = eluf(a1.z + r1.z); o1.w = eluf(a1.w + r1.w);
        float4* op = reinterpret_cast<float4*>(out);
        op[(size_t)w * 64 + lane] = o0;
        op[(size_t)w * 64 + 32 + lane] = o1;
    } else {
        float isel = (lane < 16) ? ((lane < 8) ? i0 : i1) : ((lane < 24) ? i2 : i3);
        float4 a0 = make_float4(0, 0, 0, 0);
        const float4* fp = reinterpret_cast<const float4*>(fs);
        int e = s0;
        for (; e + 4 <= s1; e += 4) {
            int sA = srcs[e], sB = srcs[e + 1], sC = srcs[e + 2], sD = srcs[e + 3];
            float4 wA = ew[e], wB = ew[e + 1], wC = ew[e + 2], wD = ew[e + 3];
            float4 fA = fp[(size_t)sA * 32 + lane];
            float4 fB = fp[(size_t)sB * 32 + lane];
            float4 fC = fp[(size_t)sC * 32 + lane];
            float4 fD = fp[(size_t)sD * 32 + lane];
            float wa;
            wa = ((lane < 16) ? ((lane < 8) ? wA.x : wA.y) : ((lane < 24) ? wA.z : wA.w)) * isel;
            a0.x = fmaf(wa, fA.x, a0.x); a0.y = fmaf(wa, fA.y, a0.y);
            a0.z = fmaf(wa, fA.z, a0.z); a0.w = fmaf(wa, fA.w, a0.w);
            wa = ((lane < 16) ? ((lane < 8) ? wB.x : wB.y) : ((lane < 24) ? wB.z : wB.w)) * isel;
            a0.x = fmaf(wa, fB.x, a0.x); a0.y = fmaf(wa, fB.y, a0.y);
            a0.z = fmaf(wa, fB.z, a0.z); a0.w = fmaf(wa, fB.w, a0.w);
            wa = ((lane < 16) ? ((lane < 8) ? wC.x : wC.y) : ((lane < 24) ? wC.z : wC.w)) * isel;
            a0.x = fmaf(wa, fC.x, a0.x); a0.y = fmaf(wa, fC.y, a0.y);
            a0.z = fmaf(wa, fC.z, a0.z); a0.w = fmaf(wa, fC.w, a0.w);
            wa = ((lane < 16) ? ((lane < 8) ? wD.x : wD.y) : ((lane < 24) ? wD.z : wD.w)) * isel;
            a0.x = fmaf(wa, fD.x, a0.x); a0.y = fmaf(wa, fD.y, a0.y);
            a0.z = fmaf(wa, fD.z, a0.z); a0.w = fmaf(wa, fD.w, a0.w);
        }
        for (; e < s1; e++) {
            int s = srcs[e];
            float4 w4 = ew[e];
            float wa = ((lane < 16) ? ((lane < 8) ? w4.x : w4.y)
                                    : ((lane < 24) ? w4.z : w4.w)) * isel;
            float4 f0 = fp[(size_t)s * 32 + lane];
            a0.x = fmaf(wa, f0.x, a0.x); a0.y = fmaf(wa, f0.y, a0.y);
            a0.z = fmaf(wa, f0.z, a0.z); a0.w = fmaf(wa, f0.w, a0.w);
        }
        const float4* rp = reinterpret_cast<const float4*>(resid);
        float4 r = rp[(size_t)w * 32 + lane];
        float4 v;
        v.x = a0.x + r.x; v.y = a0.y + r.y; v.z = a0.z + r.z; v.w = a0.w + r.w;
        v.x += __shfl_xor_sync(0xffffffffu, v.x, 8);
        v.y += __shfl_xor_sync(0xffffffffu, v.y, 8);
        v.z += __shfl_xor_sync(0xffffffffu, v.z, 8);
        v.w += __shfl_xor_sync(0xffffffffu, v.w, 8);
        v.x += __shfl_xor_sync(0xffffffffu, v.x, 16);
        v.y += __shfl_xor_sync(0xffffffffu, v.y, 16);
        v.z += __shfl_xor_sync(0xffffffffu, v.z, 16);
        v.w += __shfl_xor_sync(0xffffffffu, v.w, 16);
        if (lane < 8) {
            v.x *= 0.25f; v.y *= 0.25f; v.z *= 0.25f; v.w *= 0.25f;
            reinterpret_cast<float4*>(out)[(size_t)w * 8 + lane] = v;
        }
    }
}

// ---------------- launcher (R9 scheduling; fp16 GEMM1 only) ----------------
extern "C" void kernel_launch(void* const* d_in, const int* in_sizes, int n_in,
                              void* d_out, int out_size) {
    const float* h   = (const float*)d_in[0];
    const int*   src = (const int*)d_in[1];
    const int*   dst = (const int*)d_in[2];
    const float* W1s = (const float*)d_in[3];
    const float* W1d = (const float*)d_in[4];
    const float* al1 = (const float*)d_in[5];
    const float* ar1 = (const float*)d_in[6];
    const float* W2s = (const float*)d_in[7];
    const float* W2d = (const float*)d_in[8];
    const float* al2 = (const float*)d_in[9];
    const float* ar2 = (const float*)d_in[10];
    const float* Wr2 = (const float*)d_in[11];
    float* out = (float*)d_out;

    int Nn = in_sizes[0] / 256;
    int E  = in_sizes[1];
    if (Nn > NMAX) Nn = NMAX;
    if (E  > EMAX) E  = EMAX;

    float *fs1, *h1, *fs2, *res2, *VU1, *VU2;
    __half *h16, *w1s16;
    float4 *el1, *er1, *el2, *er2, *ew;
    int *rowptr, *cursor, *deg, *srcs, *bsum;
    cudaGetSymbolAddress((void**)&fs1,    g_fs1);
    cudaGetSymbolAddress((void**)&h1,     g_h1);
    cudaGetSymbolAddress((void**)&fs2,    g_fs2);
    cudaGetSymbolAddress((void**)&res2,   g_res2);
    cudaGetSymbolAddress((void**)&h16,    g_h16);
    cudaGetSymbolAddress((void**)&w1s16,  g_w1s16);
    cudaGetSymbolAddress((void**)&VU1,    g_VU1);
    cudaGetSymbolAddress((void**)&VU2,    g_VU2);
    cudaGetSymbolAddress((void**)&el1,    g_el1);
    cudaGetSymbolAddress((void**)&er1,    g_er1);
    cudaGetSymbolAddress((void**)&el2,    g_el2);
    cudaGetSymbolAddress((void**)&er2,    g_er2);
    cudaGetSymbolAddress((void**)&ew,     g_ew);
    cudaGetSymbolAddress((void**)&rowptr, g_rowptr);
    cudaGetSymbolAddress((void**)&cursor, g_cursor);
    cudaGetSymbolAddress((void**)&deg,    g_deg);
    cudaGetSymbolAddress((void**)&srcs,   g_srcs);
    cudaGetSymbolAddress((void**)&bsum,   g_bsum);

    cudaFuncSetAttribute(k_gemm16, cudaFuncAttributeMaxDynamicSharedMemorySize, GEMM16_SMEM);
    cudaFuncSetAttribute(k_gemm<128, true>, cudaFuncAttributeMaxDynamicSharedMemorySize, GEMM_SMEM);

    int wblocks = (Nn * 32 + 255) / 256;
    int nch = (Nn + 1023) / 1024;
    dim3 g1((Nn + 127) / 128, 4);
    dim3 g2((Nn + 127) / 128, 4);

    cudaStream_t side;
    cudaStreamCreateWithFlags(&side, cudaStreamNonBlocking);
    cudaEvent_t evFork1, evJoin1, evFork2, evJoin2;
    cudaEventCreateWithFlags(&evFork1, cudaEventDisableTiming);
    cudaEventCreateWithFlags(&evJoin1, cudaEventDisableTiming);
    cudaEventCreateWithFlags(&evFork2, cudaEventDisableTiming);
    cudaEventCreateWithFlags(&evJoin2, cudaEventDisableTiming);

    // ---- fork 1: CSR + eler1 on side; cvt + fp16 GEMM1 on main ----
    cudaEventRecord(evFork1, 0);
    cudaStreamWaitEvent(side, evFork1, 0);

    k_zero<<<(Nn + 255) / 256, 256, 0, side>>>(deg, Nn);
    k_hist<<<(E + 255) / 256, 256, 0, side>>>(dst, deg, E);
    k_scan_chunk<<<nch, 1024, 0, side>>>(deg, rowptr, bsum, Nn);
    k_scan_add<<<(Nn + 255) / 256, 256, 0, side>>>(rowptr, cursor, bsum, Nn, E, nch);
    k_scatter<<<(E + 255) / 256, 256, 0, side>>>(src, dst, cursor, srcs, E);
    k_vecs<64><<<8, 256, 0, side>>>(W1s, al1, W1d, ar1, VU1);
    k_eler<<<wblocks, 256, 0, side>>>(h, VU1, el1, er1, Nn);
    cudaEventRecord(evJoin1, side);

    k_cvt<<<(Nn * 64 + 255) / 256, 256>>>(h, h16, Nn * 64);
    k_cvt<<<(256 * 256 / 4 + 255) / 256, 256>>>(W1s, w1s16, 256 * 256 / 4);
    k_gemm16<<<g1, 256, GEMM16_SMEM>>>(h16, w1s16, fs1, Nn);

    cudaStreamWaitEvent(0, evJoin1, 0);
    k_agg<true><<<wblocks, 256>>>(rowptr, srcs, el1, er1, fs1, h, h1, ew, Nn);

    // ---- fork 2: eler2 on side; combined tf32 GEMM2 (fs2 + res2) on main ----
    cudaEventRecord(evFork2, 0);
    cudaStreamWaitEvent(side, evFork2, 0);

    k_vecs<32><<<8, 256, 0, side>>>(W2s, al2, W2d, ar2, VU2);
    k_eler<<<wblocks, 256, 0, side>>>(h1, VU2, el2, er2, Nn);
    cudaEventRecord(evJoin2, side);

    k_gemm<128, true><<<g2, 256, GEMM_SMEM>>>(h1, W2s, Wr2, fs2, res2, Nn);

    cudaStreamWaitEvent(0, evJoin2, 0);
    k_agg<false><<<wblocks, 256>>>(rowptr, srcs, el2, er2, fs2, res2, out, ew, Nn);
}